// round 1
// baseline (speedup 1.0000x reference)
#include <cuda_runtime.h>
#include <cuda_bf16.h>

#define N_NODES 50000
#define N_EDGES 1600000
#define C_OUT   256

// ---------------- scratch (static device globals; allocation-free) ----------
__device__ int   g_is64;
__device__ int   g_src[N_EDGES];
__device__ int   g_dst[N_EDGES];
__device__ float g_ew[N_EDGES];
__device__ int   g_srcS[N_EDGES];
__device__ float g_ewS[N_EDGES];
__device__ int   g_deg[N_NODES];
__device__ int   g_rowoff[N_NODES + 1];
__device__ int   g_cursor[N_NODES];
__device__ float g_agg[(size_t)N_NODES * C_OUT];
__device__ float g_h[(size_t)N_NODES * C_OUT];

// ---------------- int64-vs-int32 edge_index detection -----------------------
// If edge_index is int64 (little-endian, values < 50000), every odd 32-bit
// word of the first 64 entries is 0. Under int32, 64 random values in
// [0,50000) being all zero has probability ~(2e-5)^64 — impossible.
__global__ void detect_kernel(const int* __restrict__ ei_words) {
    __shared__ int nz;
    if (threadIdx.x == 0) nz = 0;
    __syncthreads();
    if (ei_words[2 * threadIdx.x + 1] != 0) atomicOr(&nz, 1);
    __syncthreads();
    if (threadIdx.x == 0) g_is64 = (nz == 0) ? 1 : 0;
}

__global__ void zero_deg_kernel() {
    int i = blockIdx.x * blockDim.x + threadIdx.x;
    if (i < N_NODES) g_deg[i] = 0;
}

// decode edge_index, compute ew = mean(edge_attr, -1), histogram dst degrees
__global__ void build_edges_kernel(const int* __restrict__ ei,
                                   const float* __restrict__ ea) {
    int e = blockIdx.x * blockDim.x + threadIdx.x;
    if (e >= N_EDGES) return;
    int s, d;
    if (g_is64) {
        s = ei[2 * (size_t)e];
        d = ei[2 * (size_t)N_EDGES + 2 * (size_t)e];
    } else {
        s = ei[e];
        d = ei[N_EDGES + e];
    }
    g_src[e] = s;
    g_dst[e] = d;
    const float4* a4 = (const float4*)(ea + (size_t)e * 8);
    float4 u = a4[0];
    float4 v = a4[1];
    g_ew[e] = (u.x + u.y + u.z + u.w + v.x + v.y + v.z + v.w) * 0.125f;
    atomicAdd(&g_deg[d], 1);
}

// single-block exclusive scan over g_deg -> g_rowoff, g_cursor
__global__ void scan_kernel() {
    __shared__ int sh[1024];
    int tid = threadIdx.x;
    int carry = 0;
    for (int base = 0; base < N_NODES; base += 1024) {
        int i = base + tid;
        int v = (i < N_NODES) ? g_deg[i] : 0;
        sh[tid] = v;
        __syncthreads();
#pragma unroll
        for (int off = 1; off < 1024; off <<= 1) {
            int t = (tid >= off) ? sh[tid - off] : 0;
            __syncthreads();
            sh[tid] += t;
            __syncthreads();
        }
        int incl = sh[tid];
        if (i < N_NODES) {
            int ex = carry + incl - v;
            g_rowoff[i] = ex;
            g_cursor[i] = ex;
        }
        carry += sh[1023];
        __syncthreads();
    }
    if (tid == 0) g_rowoff[N_NODES] = carry;
}

// scatter edges into CSR buckets (sorted by dst)
__global__ void fill_kernel() {
    int e = blockIdx.x * blockDim.x + threadIdx.x;
    if (e >= N_EDGES) return;
    int d = g_dst[e];
    int p = atomicAdd(&g_cursor[d], 1);
    g_srcS[p] = g_src[e];
    g_ewS[p] = g_ew[e];
}

// ---------------- gather-aggregate: out[i] = sum_{e: dst=i} in[src_e] * w_e --
// One node per 64-lane (C=256) / 32-lane (C=128) group, float4 per lane.
template <int C, bool USE_W>
__global__ void gather_kernel(const float* __restrict__ in,
                              float* __restrict__ out) {
    constexpr int L = C / 4;        // lanes per node
    constexpr int G = 256 / L;      // nodes per 256-thread block
    int grp  = threadIdx.x / L;
    int lane = threadIdx.x % L;
    int node = blockIdx.x * G + grp;
    if (node >= N_NODES) return;

    int e0 = g_rowoff[node];
    int e1 = g_rowoff[node + 1];
    const float4* in4 = (const float4*)in;
    float4 acc = make_float4(0.f, 0.f, 0.f, 0.f);

    int e = e0;
    for (; e + 2 <= e1; e += 2) {
        int sa = g_srcS[e];
        int sb = g_srcS[e + 1];
        float wa = USE_W ? g_ewS[e] : 1.0f;
        float wb = USE_W ? g_ewS[e + 1] : 1.0f;
        float4 va = in4[(size_t)sa * L + lane];
        float4 vb = in4[(size_t)sb * L + lane];
        acc.x = fmaf(va.x, wa, acc.x);
        acc.y = fmaf(va.y, wa, acc.y);
        acc.z = fmaf(va.z, wa, acc.z);
        acc.w = fmaf(va.w, wa, acc.w);
        acc.x = fmaf(vb.x, wb, acc.x);
        acc.y = fmaf(vb.y, wb, acc.y);
        acc.z = fmaf(vb.z, wb, acc.z);
        acc.w = fmaf(vb.w, wb, acc.w);
    }
    if (e < e1) {
        int sa = g_srcS[e];
        float wa = USE_W ? g_ewS[e] : 1.0f;
        float4 va = in4[(size_t)sa * L + lane];
        acc.x = fmaf(va.x, wa, acc.x);
        acc.y = fmaf(va.y, wa, acc.y);
        acc.z = fmaf(va.z, wa, acc.z);
        acc.w = fmaf(va.w, wa, acc.w);
    }
    ((float4*)out)[(size_t)node * L + lane] = acc;
}

// ---------------- GEMM: out[M,256] = A[M,K] @ W[256,K]^T + epilogue ---------
// BM=BN=64, BK=16, 256 threads, 4x4 register tile per thread.
template <int K, bool BN_RELU>
__global__ void gemm_kernel(const float* __restrict__ A,
                            const float* __restrict__ W,
                            const float* __restrict__ bias,
                            const float* __restrict__ gam,
                            const float* __restrict__ bet,
                            const float* __restrict__ mu,
                            const float* __restrict__ var,
                            float* __restrict__ out) {
    constexpr int BM = 64, BN = 64, BK = 16;
    __shared__ float As[BK][BM];
    __shared__ float Bs[BK][BN];

    int m0 = blockIdx.x * BM;
    int n0 = blockIdx.y * BN;
    int tid = threadIdx.x;
    int tx = tid % 16;   // output col group
    int ty = tid / 16;   // output row group

    int lr = tid / 4;          // 0..63 : tile row (A) / weight row n (B)
    int lk = (tid % 4) * 4;    // 0,4,8,12 : k offset

    float acc[4][4];
#pragma unroll
    for (int i = 0; i < 4; i++)
#pragma unroll
        for (int j = 0; j < 4; j++) acc[i][j] = 0.f;

    for (int k0 = 0; k0 < K; k0 += BK) {
        {
            int row = m0 + lr;
            float4 v = make_float4(0.f, 0.f, 0.f, 0.f);
            if (row < N_NODES)
                v = *(const float4*)(A + (size_t)row * K + k0 + lk);
            As[lk + 0][lr] = v.x;
            As[lk + 1][lr] = v.y;
            As[lk + 2][lr] = v.z;
            As[lk + 3][lr] = v.w;

            float4 w = *(const float4*)(W + (size_t)(n0 + lr) * K + k0 + lk);
            Bs[lk + 0][lr] = w.x;
            Bs[lk + 1][lr] = w.y;
            Bs[lk + 2][lr] = w.z;
            Bs[lk + 3][lr] = w.w;
        }
        __syncthreads();
#pragma unroll
        for (int k = 0; k < BK; k++) {
            float4 a = *(const float4*)&As[k][ty * 4];
            float4 b = *(const float4*)&Bs[k][tx * 4];
            float ar[4] = {a.x, a.y, a.z, a.w};
            float br[4] = {b.x, b.y, b.z, b.w};
#pragma unroll
            for (int i = 0; i < 4; i++)
#pragma unroll
                for (int j = 0; j < 4; j++)
                    acc[i][j] = fmaf(ar[i], br[j], acc[i][j]);
        }
        __syncthreads();
    }

    // epilogue: +bias, optional BN(eval)+ReLU, float4 store
    int nbase = n0 + tx * 4;
    float bb[4], ss[4], tt[4];
#pragma unroll
    for (int j = 0; j < 4; j++) {
        bb[j] = bias[nbase + j];
        if (BN_RELU) {
            float inv = gam[nbase + j] * rsqrtf(var[nbase + j] + 1e-5f);
            ss[j] = inv;
            tt[j] = bet[nbase + j] - mu[nbase + j] * inv;
        }
    }
#pragma unroll
    for (int i = 0; i < 4; i++) {
        int m = m0 + ty * 4 + i;
        if (m < N_NODES) {
            float z[4];
#pragma unroll
            for (int j = 0; j < 4; j++) {
                float v = acc[i][j] + bb[j];
                if (BN_RELU) v = fmaxf(fmaf(v, ss[j], tt[j]), 0.f);
                z[j] = v;
            }
            *(float4*)(out + (size_t)m * C_OUT + nbase) =
                make_float4(z[0], z[1], z[2], z[3]);
        }
    }
}

// ---------------- launch ----------------------------------------------------
extern "C" void kernel_launch(void* const* d_in, const int* in_sizes, int n_in,
                              void* d_out, int out_size) {
    const float* x   = (const float*)d_in[0];
    const int*   ei  = (const int*)d_in[1];   // int32 or int64 words, detected
    const float* ea  = (const float*)d_in[2];
    const float* W1  = (const float*)d_in[3];
    const float* b1  = (const float*)d_in[4];
    const float* g1  = (const float*)d_in[5];
    const float* be1 = (const float*)d_in[6];
    const float* m1  = (const float*)d_in[7];
    const float* v1  = (const float*)d_in[8];
    const float* W2  = (const float*)d_in[9];
    const float* b2  = (const float*)d_in[10];
    const float* g2  = (const float*)d_in[11];
    const float* be2 = (const float*)d_in[12];
    const float* m2  = (const float*)d_in[13];
    const float* v2  = (const float*)d_in[14];
    const float* W3  = (const float*)d_in[15];
    const float* b3  = (const float*)d_in[16];
    float* out = (float*)d_out;

    void *p_agg, *p_h;
    cudaGetSymbolAddress(&p_agg, g_agg);
    cudaGetSymbolAddress(&p_h, g_h);
    float* agg = (float*)p_agg;
    float* h   = (float*)p_h;

    // ---- CSR build (once, reused by all 3 layers) ----
    detect_kernel<<<1, 64>>>(ei);
    zero_deg_kernel<<<(N_NODES + 255) / 256, 256>>>();
    build_edges_kernel<<<(N_EDGES + 255) / 256, 256>>>(ei, ea);
    scan_kernel<<<1, 1024>>>();
    fill_kernel<<<(N_EDGES + 255) / 256, 256>>>();

    dim3 ggrid(782, 4);  // ceil(50000/64) x (256/64)

    // ---- layer 1: aggregate x (C=128), GEMM K=128 + BN1 + ReLU ----
    gather_kernel<128, true><<<(N_NODES + 7) / 8, 256>>>(x, agg);
    gemm_kernel<128, true><<<ggrid, 256>>>(agg, W1, b1, g1, be1, m1, v1, h);

    // ---- layer 2: aggregate h (C=256), GEMM K=256 + BN2 + ReLU ----
    gather_kernel<256, true><<<(N_NODES + 3) / 4, 256>>>(h, agg);
    gemm_kernel<256, true><<<ggrid, 256>>>(agg, W2, b2, g2, be2, m2, v2, h);

    // ---- layer 3: aggregate h (C=256, no edge weight), GEMM K=256 + bias ----
    gather_kernel<256, false><<<(N_NODES + 3) / 4, 256>>>(h, agg);
    gemm_kernel<256, false><<<ggrid, 256>>>(agg, W3, b3, nullptr, nullptr,
                                            nullptr, nullptr, out);
}